// round 5
// baseline (speedup 1.0000x reference)
#include <cuda_runtime.h>
#include <cuda_fp16.h>
#include <math.h>

// ---- problem constants ----
#define NL 12
#define NH 12
#define NC 768
#define NV 50257
#define NT 1024
#define NB 4
#define ND 64
#define NTOK (NB * NT)   // 4096

// ---- fp32 activation scratch ----
__device__ float g_x[NTOK * NC];
__device__ float g_h[NTOK * NC];
__device__ float g_qkv[NTOK * 3 * NC];
__device__ float g_y[NTOK * NC];
__device__ float g_fc[NTOK * 4 * NC];

// ---- pre-split fp16 weight scratch (hi/lo planes, [N][K] layout) ----
__device__ __half g_wa_h[12 * 2304 * 768], g_wa_l[12 * 2304 * 768];
__device__ __half g_wp_h[12 * 768 * 768],  g_wp_l[12 * 768 * 768];
__device__ __half g_wf_h[12 * 3072 * 768], g_wf_l[12 * 3072 * 768];
__device__ __half g_wq_h[12 * 768 * 3072], g_wq_l[12 * 768 * 3072];
__device__ __half g_lm_h[50257 * 768],     g_lm_l[50257 * 768];

// =====================================================================
// Weight conversion: transpose [K][N] fp32 -> [N][K] fp16 hi/lo
// =====================================================================
__global__ void transpose_split(const float* __restrict__ W,
                                __half* __restrict__ OH, __half* __restrict__ OL,
                                int K, int N) {
    __shared__ float t[32][33];
    int l = blockIdx.z;
    const float* Wl = W + (size_t)l * K * N;
    __half* OHl = OH + (size_t)l * K * N;
    __half* OLl = OL + (size_t)l * K * N;
    int n0 = blockIdx.x * 32, k0 = blockIdx.y * 32;
    int tx = threadIdx.x, ty = threadIdx.y;
    #pragma unroll
    for (int i = ty; i < 32; i += 8)
        t[i][tx] = Wl[(size_t)(k0 + i) * N + n0 + tx];
    __syncthreads();
    #pragma unroll
    for (int i = ty; i < 32; i += 8) {
        float v = t[tx][i];
        __half h = __float2half_rn(v);
        OHl[(size_t)(n0 + i) * K + k0 + tx] = h;
        OLl[(size_t)(n0 + i) * K + k0 + tx] = __float2half_rn(v - __half2float(h));
    }
}

// lm_head is already [N][K]: elementwise split only
__global__ void split_kernel(const float* __restrict__ W,
                             __half* __restrict__ H, __half* __restrict__ L,
                             int n) {
    int i = blockIdx.x * blockDim.x + threadIdx.x;
    if (i < n) {
        float x = W[i];
        __half h = __float2half_rn(x);
        H[i] = h;
        L[i] = __float2half_rn(x - __half2float(h));
    }
}

// =====================================================================
// Embedding
// =====================================================================
__global__ void embed_kernel(const int* __restrict__ idx,
                             const float* __restrict__ wte,
                             const float* __restrict__ wpe,
                             float* __restrict__ x) {
    int row = blockIdx.x;
    int t = row % NT;
    int tok = idx[row];
    const float* we = wte + (size_t)tok * NC;
    const float* wp = wpe + (size_t)t * NC;
    float* out = x + (size_t)row * NC;
    for (int c = threadIdx.x; c < NC; c += blockDim.x)
        out[c] = we[c] + wp[c];
}

// =====================================================================
// LayerNorm
// =====================================================================
__global__ void ln_kernel(const float* __restrict__ x,
                          const float* __restrict__ w,
                          const float* __restrict__ b,
                          float* __restrict__ out) {
    int row = blockIdx.x;
    const float* xr = x + (size_t)row * NC;
    __shared__ float red[32];
    int tid = threadIdx.x;
    int nwarp = blockDim.x >> 5;

    float s = 0.f;
    for (int c = tid; c < NC; c += blockDim.x) s += xr[c];
    #pragma unroll
    for (int o = 16; o; o >>= 1) s += __shfl_xor_sync(0xffffffffu, s, o);
    if ((tid & 31) == 0) red[tid >> 5] = s;
    __syncthreads();
    if (tid < 32) {
        float v = (tid < nwarp) ? red[tid] : 0.f;
        #pragma unroll
        for (int o = 16; o; o >>= 1) v += __shfl_xor_sync(0xffffffffu, v, o);
        if (tid == 0) red[0] = v;
    }
    __syncthreads();
    float mu = red[0] * (1.0f / NC);
    __syncthreads();

    float s2 = 0.f;
    for (int c = tid; c < NC; c += blockDim.x) {
        float d = xr[c] - mu;
        s2 += d * d;
    }
    #pragma unroll
    for (int o = 16; o; o >>= 1) s2 += __shfl_xor_sync(0xffffffffu, s2, o);
    if ((tid & 31) == 0) red[tid >> 5] = s2;
    __syncthreads();
    if (tid < 32) {
        float v = (tid < nwarp) ? red[tid] : 0.f;
        #pragma unroll
        for (int o = 16; o; o >>= 1) v += __shfl_xor_sync(0xffffffffu, v, o);
        if (tid == 0) red[0] = v;
    }
    __syncthreads();
    float var = red[0] * (1.0f / NC);
    float rstd = rsqrtf(var + 1e-5f);
    float* outr = out + (size_t)row * NC;
    for (int c = tid; c < NC; c += blockDim.x)
        outr[c] = (xr[c] - mu) * rstd * w[c] + b[c];
}

// =====================================================================
// fp16 split-GEMM (NT): C[M,N] = A[M,K] @ B[N,K]^T  (+bias)(gelu?)(+res)
// A fp32 (split on the fly), B pre-split fp16 hi/lo.
// block 128x128x32, 8 warps (warp tile 64x32), double-buffered smem.
// =====================================================================
#define HBM 128
#define HBN 128
#define HBK 32
#define RS 20                 // row stride in uint32 (16 data + 4 pad)
#define PL (128 * RS)         // plane size in uint32 = 2560
#define HSMEM_BYTES (2 * 4 * PL * 4)   // 81920

__device__ __forceinline__ float gelu_f(float u) {
    return 0.5f * u * (1.0f + tanhf(0.7978845608028654f * (u + 0.044715f * u * u * u)));
}

__device__ __forceinline__ void mma_f16(float* c, const unsigned* a,
                                        unsigned b0, unsigned b1) {
    asm volatile(
        "mma.sync.aligned.m16n8k16.row.col.f32.f16.f16.f32 "
        "{%0,%1,%2,%3}, {%4,%5,%6,%7}, {%8,%9}, {%0,%1,%2,%3};"
        : "+f"(c[0]), "+f"(c[1]), "+f"(c[2]), "+f"(c[3])
        : "r"(a[0]), "r"(a[1]), "r"(a[2]), "r"(a[3]), "r"(b0), "r"(b1));
}

__device__ __forceinline__ unsigned pack_h2(__half a, __half b) {
    __half2 h = __halves2half2(a, b);
    return *reinterpret_cast<unsigned*>(&h);
}

__device__ __forceinline__ void ldg_A(const float* A, int bm, int K, int kbase,
                                      int ar, int ak, float4* r) {
    #pragma unroll
    for (int i = 0; i < 4; i++)
        r[i] = *(const float4*)(A + (size_t)(bm + ar) * K + kbase + ak + 4 * i);
}

__device__ __forceinline__ void sts_A(unsigned* AsH, unsigned* AsL,
                                      int ar, int ak, const float4* r) {
    #pragma unroll
    for (int i = 0; i < 4; i++) {
        float4 v = r[i];
        int cu = (ak + 4 * i) >> 1;
        __half hx = __float2half_rn(v.x), hy = __float2half_rn(v.y);
        __half hz = __float2half_rn(v.z), hw = __float2half_rn(v.w);
        float lx = v.x - __half2float(hx), ly = v.y - __half2float(hy);
        float lz = v.z - __half2float(hz), lw = v.w - __half2float(hw);
        AsH[ar * RS + cu]     = pack_h2(hx, hy);
        AsH[ar * RS + cu + 1] = pack_h2(hz, hw);
        AsL[ar * RS + cu]     = pack_h2(__float2half_rn(lx), __float2half_rn(ly));
        AsL[ar * RS + cu + 1] = pack_h2(__float2half_rn(lz), __float2half_rn(lw));
    }
}

__device__ __forceinline__ void load_B(const __half* Bh, const __half* Bl,
                                       unsigned* BsH, unsigned* BsL,
                                       int bn, int N, int K, int kbase, int tid) {
    #pragma unroll
    for (int i = 0; i < 4; i++) {
        int o = i * 256 + tid;
        int p = o >> 9;
        int oo = o & 511;
        int br = oo >> 2, seg = oo & 3;
        unsigned* dst = (p ? BsL : BsH) + br * RS + seg * 4;
        int gn = bn + br;
        if (gn < N) {
            const __half* src = (p ? Bl : Bh) + (size_t)gn * K + kbase + seg * 8;
            unsigned da = (unsigned)__cvta_generic_to_shared(dst);
            asm volatile("cp.async.cg.shared.global [%0], [%1], 16;"
                         :: "r"(da), "l"(src));
        } else {
            *reinterpret_cast<uint4*>(dst) = make_uint4(0, 0, 0, 0);
        }
    }
}

__global__ void __launch_bounds__(256) hgemm_nt(
    const float* __restrict__ A,
    const __half* __restrict__ Bh, const __half* __restrict__ Bl,
    const float* __restrict__ bias, const float* __restrict__ res,
    float* __restrict__ C, int M, int N, int K, int act, int swap)
{
    extern __shared__ unsigned sm[];

    int tid = threadIdx.x;
    int lane = tid & 31, warp = tid >> 5;
    int g = lane >> 2, t4 = lane & 3;
    int wm = (warp >> 2) * 64;   // 0 / 64
    int wn = (warp & 3) * 32;    // 0..96

    int bm = (swap ? blockIdx.x : blockIdx.y) * HBM;
    int bn = (swap ? blockIdx.y : blockIdx.x) * HBN;

    int ar = tid >> 1;
    int ak = (tid & 1) * 16;

    float c[4][4][4] = {};
    float4 areg[4];

    const int S = K / HBK;

    // prologue: stage 0 into buffer 0
    ldg_A(A, bm, K, 0, ar, ak, areg);
    load_B(Bh, Bl, sm + 2 * PL, sm + 3 * PL, bn, N, K, 0, tid);
    asm volatile("cp.async.commit_group;");
    sts_A(sm, sm + PL, ar, ak, areg);
    asm volatile("cp.async.wait_group 0;");
    __syncthreads();

    for (int s = 0; s < S; s++) {
        int cur = s & 1, nxt = cur ^ 1;
        unsigned* base = sm + cur * 4 * PL;
        const unsigned* Ah = base;
        const unsigned* Al = base + PL;
        const unsigned* Bhs = base + 2 * PL;
        const unsigned* Bls = base + 3 * PL;
        unsigned* nbase = sm + nxt * 4 * PL;

        bool more = (s + 1 < S);
        if (more) {
            ldg_A(A, bm, K, (s + 1) * HBK, ar, ak, areg);
            load_B(Bh, Bl, nbase + 2 * PL, nbase + 3 * PL, bn, N, K, (s + 1) * HBK, tid);
            asm volatile("cp.async.commit_group;");
        }

        #pragma unroll
        for (int kk = 0; kk < 2; kk++) {
            int kd = kk * 8;
            unsigned ah[4][4], al[4][4];
            #pragma unroll
            for (int im = 0; im < 4; im++) {
                int r = (wm + im * 16 + g) * RS;
                int r8 = r + 8 * RS;
                ah[im][0] = Ah[r + kd + t4];
                ah[im][1] = Ah[r8 + kd + t4];
                ah[im][2] = Ah[r + kd + 4 + t4];
                ah[im][3] = Ah[r8 + kd + 4 + t4];
                al[im][0] = Al[r + kd + t4];
                al[im][1] = Al[r8 + kd + t4];
                al[im][2] = Al[r + kd + 4 + t4];
                al[im][3] = Al[r8 + kd + 4 + t4];
            }
            #pragma unroll
            for (int jn = 0; jn < 4; jn++) {
                int n = (wn + jn * 8 + g) * RS;
                unsigned bh0 = Bhs[n + kd + t4], bh1 = Bhs[n + kd + 4 + t4];
                unsigned bl0 = Bls[n + kd + t4], bl1 = Bls[n + kd + 4 + t4];
                #pragma unroll
                for (int im = 0; im < 4; im++) {
                    mma_f16(c[im][jn], ah[im], bh0, bh1);
                    mma_f16(c[im][jn], ah[im], bl0, bl1);
                    mma_f16(c[im][jn], al[im], bh0, bh1);
                }
            }
        }

        if (more)
            sts_A(nbase, nbase + PL, ar, ak, areg);
        asm volatile("cp.async.wait_group 0;");
        __syncthreads();
    }

    // epilogue
    #pragma unroll
    for (int im = 0; im < 4; im++) {
        #pragma unroll
        for (int jn = 0; jn < 4; jn++) {
            int row0 = bm + wm + im * 16 + g;
            int col0 = bn + wn + jn * 8 + t4 * 2;
            #pragma unroll
            for (int p = 0; p < 4; p++) {
                int row = row0 + (p >> 1) * 8;
                int col = col0 + (p & 1);
                if (col < N) {
                    float v = c[im][jn][p];
                    if (bias) v += bias[col];
                    if (act) v = gelu_f(v);
                    if (res) v += res[(size_t)row * N + col];
                    C[(size_t)row * N + col] = v;
                }
            }
        }
    }
}

// =====================================================================
// Causal attention (unchanged)
// =====================================================================
__global__ void attn_kernel(const float* __restrict__ qkv, float* __restrict__ y) {
    int q = blockIdx.x;
    int h = blockIdx.y;
    int b = blockIdx.z;
    int tid = threadIdx.x;

    __shared__ float qs[ND];
    __shared__ float sc[NT];
    __shared__ float red[32];
    __shared__ float yp[2][ND];

    const size_t rs = 3 * NC;
    const float* qptr = qkv + ((size_t)(b * NT + q)) * rs + h * ND;
    if (tid < ND) qs[tid] = qptr[tid];
    __syncthreads();

    const float scale = 0.125f;
    int nk = q + 1;
    const float* kbase = qkv + ((size_t)b * NT) * rs + NC + h * ND;
    for (int k = tid; k < nk; k += blockDim.x) {
        const float* kp = kbase + (size_t)k * rs;
        float d = 0.f;
        #pragma unroll
        for (int i = 0; i < ND; i++) d = fmaf(qs[i], kp[i], d);
        sc[k] = d * scale;
    }
    __syncthreads();

    float m = -1e30f;
    for (int k = tid; k < nk; k += blockDim.x) m = fmaxf(m, sc[k]);
    #pragma unroll
    for (int o = 16; o; o >>= 1) m = fmaxf(m, __shfl_xor_sync(0xffffffffu, m, o));
    if ((tid & 31) == 0) red[tid >> 5] = m;
    __syncthreads();
    if (tid < 32) {
        float v = (tid < (int)(blockDim.x >> 5)) ? red[tid] : -1e30f;
        #pragma unroll
        for (int o = 16; o; o >>= 1) v = fmaxf(v, __shfl_xor_sync(0xffffffffu, v, o));
        if (tid == 0) red[0] = v;
    }
    __syncthreads();
    m = red[0];
    __syncthreads();

    float s = 0.f;
    for (int k = tid; k < nk; k += blockDim.x) {
        float e = __expf(sc[k] - m);
        sc[k] = e;
        s += e;
    }
    #pragma unroll
    for (int o = 16; o; o >>= 1) s += __shfl_xor_sync(0xffffffffu, s, o);
    if ((tid & 31) == 0) red[tid >> 5] = s;
    __syncthreads();
    if (tid < 32) {
        float v = (tid < (int)(blockDim.x >> 5)) ? red[tid] : 0.f;
        #pragma unroll
        for (int o = 16; o; o >>= 1) v += __shfl_xor_sync(0xffffffffu, v, o);
        if (tid == 0) red[0] = v;
    }
    __syncthreads();
    float inv = 1.0f / red[0];

    int part = tid >> 6, d = tid & 63;
    const float* vbase = qkv + ((size_t)b * NT) * rs + 2 * NC + h * ND;
    float acc = 0.f;
    for (int k = part; k < nk; k += 2)
        acc = fmaf(sc[k], vbase[(size_t)k * rs + d], acc);
    yp[part][d] = acc;
    __syncthreads();
    if (tid < ND)
        y[((size_t)(b * NT + q)) * NC + h * ND + tid] = (yp[0][tid] + yp[1][tid]) * inv;
}

// =====================================================================
// launch
// =====================================================================
extern "C" void kernel_launch(void* const* d_in, const int* in_sizes, int n_in,
                              void* d_out, int out_size) {
    const int*   idx    = (const int*)d_in[0];
    const float* wte    = (const float*)d_in[1];
    const float* wpe    = (const float*)d_in[2];
    const float* ln1_w  = (const float*)d_in[3];
    const float* ln1_b  = (const float*)d_in[4];
    const float* ln2_w  = (const float*)d_in[5];
    const float* ln2_b  = (const float*)d_in[6];
    const float* attn_w = (const float*)d_in[7];
    const float* attn_b = (const float*)d_in[8];
    const float* proj_w = (const float*)d_in[9];
    const float* proj_b = (const float*)d_in[10];
    const float* fc_w   = (const float*)d_in[11];
    const float* fc_b   = (const float*)d_in[12];
    const float* fcp_w  = (const float*)d_in[13];
    const float* fcp_b  = (const float*)d_in[14];
    const float* lnf_w  = (const float*)d_in[15];
    const float* lnf_b  = (const float*)d_in[16];
    const float* lmh    = (const float*)d_in[17];
    float* out = (float*)d_out;

    float *x, *h, *qkv, *y, *fc;
    cudaGetSymbolAddress((void**)&x, g_x);
    cudaGetSymbolAddress((void**)&h, g_h);
    cudaGetSymbolAddress((void**)&qkv, g_qkv);
    cudaGetSymbolAddress((void**)&y, g_y);
    cudaGetSymbolAddress((void**)&fc, g_fc);

    __half *wa_h, *wa_l, *wp_h, *wp_l, *wf_h, *wf_l, *wq_h, *wq_l, *lm_h, *lm_l;
    cudaGetSymbolAddress((void**)&wa_h, g_wa_h);
    cudaGetSymbolAddress((void**)&wa_l, g_wa_l);
    cudaGetSymbolAddress((void**)&wp_h, g_wp_h);
    cudaGetSymbolAddress((void**)&wp_l, g_wp_l);
    cudaGetSymbolAddress((void**)&wf_h, g_wf_h);
    cudaGetSymbolAddress((void**)&wf_l, g_wf_l);
    cudaGetSymbolAddress((void**)&wq_h, g_wq_h);
    cudaGetSymbolAddress((void**)&wq_l, g_wq_l);
    cudaGetSymbolAddress((void**)&lm_h, g_lm_h);
    cudaGetSymbolAddress((void**)&lm_l, g_lm_l);

    cudaFuncSetAttribute(hgemm_nt, cudaFuncAttributeMaxDynamicSharedMemorySize,
                         HSMEM_BYTES);

    // ---- weight conversion (every launch; ~0.2 ms) ----
    dim3 tb(32, 8);
    transpose_split<<<dim3(2304 / 32, 768 / 32, 12), tb>>>(attn_w, wa_h, wa_l, NC, 3 * NC);
    transpose_split<<<dim3(768 / 32, 768 / 32, 12), tb>>>(proj_w, wp_h, wp_l, NC, NC);
    transpose_split<<<dim3(3072 / 32, 768 / 32, 12), tb>>>(fc_w, wf_h, wf_l, NC, 4 * NC);
    transpose_split<<<dim3(768 / 32, 3072 / 32, 12), tb>>>(fcp_w, wq_h, wq_l, 4 * NC, NC);
    split_kernel<<<(NV * NC + 255) / 256, 256>>>(lmh, lm_h, lm_l, NV * NC);

    embed_kernel<<<NTOK, 256>>>(idx, wte, wpe, x);

    for (int l = 0; l < NL; l++) {
        ln_kernel<<<NTOK, 256>>>(x, ln1_w + l * NC, ln1_b + l * NC, h);
        {   // qkv = h @ attn_w + attn_b
            dim3 grid((3 * NC) / HBN, NTOK / HBM);
            hgemm_nt<<<grid, 256, HSMEM_BYTES>>>(
                h, wa_h + (size_t)l * 3 * NC * NC, wa_l + (size_t)l * 3 * NC * NC,
                attn_b + (size_t)l * 3 * NC, nullptr, qkv, NTOK, 3 * NC, NC, 0, 0);
        }
        {
            dim3 grid(NT, NH, NB);
            attn_kernel<<<grid, 128>>>(qkv, y);
        }
        {   // x = x + y @ proj_w + proj_b
            dim3 grid(NC / HBN, NTOK / HBM);
            hgemm_nt<<<grid, 256, HSMEM_BYTES>>>(
                y, wp_h + (size_t)l * NC * NC, wp_l + (size_t)l * NC * NC,
                proj_b + (size_t)l * NC, x, x, NTOK, NC, NC, 0, 0);
        }
        ln_kernel<<<NTOK, 256>>>(x, ln2_w + l * NC, ln2_b + l * NC, h);
        {   // fc = gelu(h @ fc_w + fc_b)
            dim3 grid((4 * NC) / HBN, NTOK / HBM);
            hgemm_nt<<<grid, 256, HSMEM_BYTES>>>(
                h, wf_h + (size_t)l * 4 * NC * NC, wf_l + (size_t)l * 4 * NC * NC,
                fc_b + (size_t)l * 4 * NC, nullptr, fc, NTOK, 4 * NC, NC, 1, 0);
        }
        {   // x = x + fc @ fcp_w + fcp_b
            dim3 grid(NC / HBN, NTOK / HBM);
            hgemm_nt<<<grid, 256, HSMEM_BYTES>>>(
                fc, wq_h + (size_t)l * 4 * NC * NC, wq_l + (size_t)l * 4 * NC * NC,
                fcp_b + (size_t)l * NC, x, x, NTOK, NC, 4 * NC, 0, 0);
        }
    }

    ln_kernel<<<NTOK, 256>>>(x, lnf_w, lnf_b, h);

    {   // logits = h @ lm_head^T  (m-fastest grid for B-tile L2 reuse)
        dim3 grid(NTOK / HBM, (NV + HBN - 1) / HBN);
        hgemm_nt<<<grid, 256, HSMEM_BYTES>>>(
            h, lm_h, lm_l, nullptr, nullptr, out, NTOK, NV, NC, 0, 1);
    }
}

// round 7
// speedup vs baseline: 1.0389x; 1.0389x over previous
#include <cuda_runtime.h>
#include <cuda_fp16.h>
#include <math.h>
#include <stdint.h>

// ---- problem constants ----
#define NL 12
#define NH 12
#define NC 768
#define NV 50257
#define NT 1024
#define NB 4
#define ND 64
#define NTOK (NB * NT)   // 4096

// arch dispatch: tcgen05 only exists in the 'a' (arch-specific) target
#if defined(__CUDA_ARCH_FEAT_SM103_ALL) || defined(__CUDA_ARCH_FEAT_SM100_ALL) || \
    (defined(__CUDA_ARCH_SPECIFIC__) && (__CUDA_ARCH_SPECIFIC__ == 1030 || __CUDA_ARCH_SPECIFIC__ == 1000))
#define HAS_TC05 1
#else
#define HAS_TC05 0
#endif

// ---- activation scratch ----
__device__ float g_x[NTOK * NC];         // residual stream (fp32)
__device__ float g_qkv[NTOK * 3 * NC];   // qkv (fp32, read by attn)
__device__ __half g_xh[NTOK * NC],      g_xl[NTOK * NC];        // act planes (768-wide)
__device__ __half g_yh[NTOK * 4 * NC],  g_yl[NTOK * 4 * NC];    // act planes (3072-wide)

// ---- pre-split fp16 weight planes, [N][K] layout ----
__device__ __half g_wa_h[12 * 2304 * 768], g_wa_l[12 * 2304 * 768];
__device__ __half g_wp_h[12 * 768 * 768],  g_wp_l[12 * 768 * 768];
__device__ __half g_wf_h[12 * 3072 * 768], g_wf_l[12 * 3072 * 768];
__device__ __half g_wq_h[12 * 768 * 3072], g_wq_l[12 * 768 * 3072];
__device__ __half g_lm_h[50257 * 768],     g_lm_l[50257 * 768];

// =====================================================================
// small helpers
// =====================================================================
__device__ __forceinline__ uint32_t smem_u32(const void* p) {
    uint32_t a;
    asm("{ .reg .u64 t; cvta.to.shared.u64 t, %1; cvt.u32.u64 %0, t; }"
        : "=r"(a) : "l"(p));
    return a;
}

__device__ __forceinline__ void cpa16(uint32_t dst, const void* src) {
    asm volatile("cp.async.cg.shared.global [%0], [%1], 16;"
                 :: "r"(dst), "l"(src));
}

__device__ __forceinline__ uint32_t swz(uint32_t o) {   // SW128 swizzle, 16B granules
    return o ^ ((o >> 3) & 0x70);
}

__device__ __forceinline__ float gelu_f(float u) {
    return 0.5f * u * (1.0f + tanhf(0.7978845608028654f * (u + 0.044715f * u * u * u)));
}

__device__ __forceinline__ void split_h(float v, __half& hi, __half& lo) {
    hi = __float2half_rn(v);
    lo = __float2half_rn(v - __half2float(hi));
}

#if HAS_TC05
__device__ __forceinline__ uint32_t elect_one() {
    uint32_t pred;
    asm volatile(
        "{\n\t.reg .pred p;\n\telect.sync _|p, 0xFFFFFFFF;\n\t"
        "selp.b32 %0, 1, 0, p;\n\t}"
        : "=r"(pred));
    return pred;
}

__device__ __forceinline__ void mbar_wait(uint32_t mbar, uint32_t parity) {
    asm volatile(
        "{\n\t"
        ".reg .pred P1;\n\t"
        "WL%=:\n\t"
        "mbarrier.try_wait.parity.acquire.cta.shared::cta.b64 P1, [%0], %1, 0x989680;\n\t"
        "@P1 bra.uni WD%=;\n\t"
        "bra.uni WL%=;\n\t"
        "WD%=:\n\t"
        "}"
        :: "r"(mbar), "r"(parity) : "memory");
}

__device__ __forceinline__ uint64_t mk_desc(uint32_t addr) {
    // SW128, version=1 (Blackwell), SBO=64 (1024B), LBO=1 (16B)
    return 0x4000404000010000ULL | ((uint64_t)(addr >> 4) & 0x3FFF);
}

__device__ __forceinline__ void tc05_mma_f16_ss(uint32_t d, uint64_t ad, uint64_t bd,
                                                uint32_t idesc, uint32_t en) {
    asm volatile(
        "{\n\t"
        ".reg .pred p;\n\t"
        "setp.ne.u32 p, %4, 0;\n\t"
        "tcgen05.mma.cta_group::1.kind::f16 [%0], %1, %2, %3, {%5,%5,%5,%5}, p;\n\t"
        "}"
        :: "r"(d), "l"(ad), "l"(bd), "r"(idesc), "r"(en), "r"(0u)
        : "memory");
}

__device__ __forceinline__ void ldtm_x32(uint32_t* r, uint32_t addr) {
    asm volatile(
        "tcgen05.ld.sync.aligned.32x32b.x32.b32 "
        "{%0, %1, %2, %3, %4, %5, %6, %7, "
        " %8, %9, %10, %11, %12, %13, %14, %15, "
        " %16, %17, %18, %19, %20, %21, %22, %23, "
        " %24, %25, %26, %27, %28, %29, %30, %31}, [%32];"
        : "=r"(r[0]),  "=r"(r[1]),  "=r"(r[2]),  "=r"(r[3]),
          "=r"(r[4]),  "=r"(r[5]),  "=r"(r[6]),  "=r"(r[7]),
          "=r"(r[8]),  "=r"(r[9]),  "=r"(r[10]), "=r"(r[11]),
          "=r"(r[12]), "=r"(r[13]), "=r"(r[14]), "=r"(r[15]),
          "=r"(r[16]), "=r"(r[17]), "=r"(r[18]), "=r"(r[19]),
          "=r"(r[20]), "=r"(r[21]), "=r"(r[22]), "=r"(r[23]),
          "=r"(r[24]), "=r"(r[25]), "=r"(r[26]), "=r"(r[27]),
          "=r"(r[28]), "=r"(r[29]), "=r"(r[30]), "=r"(r[31])
        : "r"(addr));
}
#else
__device__ __forceinline__ void mma_f16(float* c, const unsigned* a,
                                        unsigned b0, unsigned b1) {
    asm volatile(
        "mma.sync.aligned.m16n8k16.row.col.f32.f16.f16.f32 "
        "{%0,%1,%2,%3}, {%4,%5,%6,%7}, {%8,%9}, {%0,%1,%2,%3};"
        : "+f"(c[0]), "+f"(c[1]), "+f"(c[2]), "+f"(c[3])
        : "r"(a[0]), "r"(a[1]), "r"(a[2]), "r"(a[3]), "r"(b0), "r"(b1));
}
#endif

// =====================================================================
// Weight conversion kernels
// =====================================================================
__global__ void transpose_split(const float* __restrict__ W,
                                __half* __restrict__ OH, __half* __restrict__ OL,
                                int K, int N) {
    __shared__ float t[32][33];
    int l = blockIdx.z;
    const float* Wl = W + (size_t)l * K * N;
    __half* OHl = OH + (size_t)l * K * N;
    __half* OLl = OL + (size_t)l * K * N;
    int n0 = blockIdx.x * 32, k0 = blockIdx.y * 32;
    int tx = threadIdx.x, ty = threadIdx.y;
    #pragma unroll
    for (int i = ty; i < 32; i += 8)
        t[i][tx] = Wl[(size_t)(k0 + i) * N + n0 + tx];
    __syncthreads();
    #pragma unroll
    for (int i = ty; i < 32; i += 8) {
        float v = t[tx][i];
        __half h, lo;
        split_h(v, h, lo);
        OHl[(size_t)(n0 + i) * K + k0 + tx] = h;
        OLl[(size_t)(n0 + i) * K + k0 + tx] = lo;
    }
}

__global__ void split_kernel(const float* __restrict__ W,
                             __half* __restrict__ H, __half* __restrict__ L,
                             int n) {
    int i = blockIdx.x * blockDim.x + threadIdx.x;
    if (i < n) {
        __half h, lo;
        split_h(W[i], h, lo);
        H[i] = h;
        L[i] = lo;
    }
}

// =====================================================================
// Embedding
// =====================================================================
__global__ void embed_kernel(const int* __restrict__ idx,
                             const float* __restrict__ wte,
                             const float* __restrict__ wpe,
                             float* __restrict__ x) {
    int row = blockIdx.x;
    int t = row % NT;
    int tok = idx[row];
    const float* we = wte + (size_t)tok * NC;
    const float* wp = wpe + (size_t)t * NC;
    float* out = x + (size_t)row * NC;
    for (int c = threadIdx.x; c < NC; c += blockDim.x)
        out[c] = we[c] + wp[c];
}

// =====================================================================
// LayerNorm -> fp16 hi/lo planes
// =====================================================================
__global__ void ln_kernel(const float* __restrict__ x,
                          const float* __restrict__ w,
                          const float* __restrict__ b,
                          __half* __restrict__ oh, __half* __restrict__ ol) {
    int row = blockIdx.x;
    const float* xr = x + (size_t)row * NC;
    __shared__ float red[32];
    int tid = threadIdx.x;
    int nwarp = blockDim.x >> 5;

    float s = 0.f;
    for (int c = tid; c < NC; c += blockDim.x) s += xr[c];
    #pragma unroll
    for (int o = 16; o; o >>= 1) s += __shfl_xor_sync(0xffffffffu, s, o);
    if ((tid & 31) == 0) red[tid >> 5] = s;
    __syncthreads();
    if (tid < 32) {
        float v = (tid < nwarp) ? red[tid] : 0.f;
        #pragma unroll
        for (int o = 16; o; o >>= 1) v += __shfl_xor_sync(0xffffffffu, v, o);
        if (tid == 0) red[0] = v;
    }
    __syncthreads();
    float mu = red[0] * (1.0f / NC);
    __syncthreads();

    float s2 = 0.f;
    for (int c = tid; c < NC; c += blockDim.x) {
        float d = xr[c] - mu;
        s2 += d * d;
    }
    #pragma unroll
    for (int o = 16; o; o >>= 1) s2 += __shfl_xor_sync(0xffffffffu, s2, o);
    if ((tid & 31) == 0) red[tid >> 5] = s2;
    __syncthreads();
    if (tid < 32) {
        float v = (tid < nwarp) ? red[tid] : 0.f;
        #pragma unroll
        for (int o = 16; o; o >>= 1) v += __shfl_xor_sync(0xffffffffu, v, o);
        if (tid == 0) red[0] = v;
    }
    __syncthreads();
    float var = red[0] * (1.0f / NC);
    float rstd = rsqrtf(var + 1e-5f);
    for (int c = tid; c < NC; c += blockDim.x) {
        float v = (xr[c] - mu) * rstd * w[c] + b[c];
        __half h, lo;
        split_h(v, h, lo);
        oh[(size_t)row * NC + c] = h;
        ol[(size_t)row * NC + c] = lo;
    }
}

// =====================================================================
// GEMM (NT): C[M,N] = A[M,K] @ B[N,K]^T, fp16 hi/lo 3-pass split.
// CTA tile 128x128, K chunks of 64, 256 threads, double-buffered smem.
// Body: tcgen05 (sm_103a cubin) or mma.sync fallback (sm_103 base).
// Both bodies share the SW128-swizzled smem layout + cp.async loader.
// =====================================================================
#define GBM 128
#define GBN 128
#define GKC 64
#define PLANE_B 16384                 // 128 rows x 128 bytes
#define STAGE_B (4 * PLANE_B)         // Ah, Al, Bh, Bl
#define GSMEM_BYTES (2 * STAGE_B + 1024)

#define IDESC_F16 ((1u << 4) | (16u << 17) | (8u << 24))   // f32 acc, f16, N=128, M=128

__device__ __forceinline__ void stage_load(uint32_t sb,
                                           const __half* Ah, const __half* Al,
                                           const __half* Bh, const __half* Bl,
                                           int bm, int bn, int N, int K, int k0,
                                           int tid) {
    #pragma unroll
    for (int i = 0; i < 16; i++) {
        int id = i * 256 + tid;           // 0..4095 granules of 16B
        int p = id >> 10;                 // plane 0..3
        int cid = id & 1023;
        int row = cid >> 3, c16 = cid & 7;
        uint32_t off = (uint32_t)(row * 128 + c16 * 16);
        uint32_t dst = sb + p * PLANE_B + swz(off);
        if (p < 2) {
            const __half* src = (p ? Al : Ah) + (size_t)(bm + row) * K + k0 + c16 * 8;
            cpa16(dst, src);
        } else {
            int gn = bn + row;
            if (gn < N) {
                const __half* src = (p == 3 ? Bl : Bh) + (size_t)gn * K + k0 + c16 * 8;
                cpa16(dst, src);
            }
        }
    }
}

__global__ void __launch_bounds__(256) tc05_gemm(
    const __half* __restrict__ Ah, const __half* __restrict__ Al,
    const __half* __restrict__ Bh, const __half* __restrict__ Bl,
    const float* __restrict__ bias, const float* __restrict__ res,
    float* __restrict__ Cf, __half* __restrict__ Ch, __half* __restrict__ Cl,
    int M, int N, int K, int act)
{
    extern __shared__ char dsm[];
    uint32_t sbase = (smem_u32(dsm) + 1023) & ~1023u;

    int tid = threadIdx.x;
    int lane = tid & 31, warp = tid >> 5;
    int bm = blockIdx.x * GBM;
    int bn = blockIdx.y * GBN;
    const int S = K / GKC;

#if HAS_TC05
    // ================= tcgen05 path =================
    __shared__ uint32_t s_tmem;
    __shared__ uint64_t s_mbar;
    uint32_t mbar = smem_u32(&s_mbar);

    if (warp == 0) {
        asm volatile("tcgen05.alloc.cta_group::1.sync.aligned.shared::cta.b32 [%0], %1;"
                     :: "r"(smem_u32(&s_tmem)), "r"(128u) : "memory");
    }
    if (tid == 0) {
        asm volatile("mbarrier.init.shared.b64 [%0], 1;" :: "r"(mbar) : "memory");
    }
    __syncthreads();
    uint32_t tmem;
    asm volatile("ld.shared.b32 %0, [%1];" : "=r"(tmem) : "r"(smem_u32(&s_tmem)));

    stage_load(sbase, Ah, Al, Bh, Bl, bm, bn, N, K, 0, tid);
    asm volatile("cp.async.commit_group;");

    for (int s = 0; s < S; s++) {
        if (s >= 1) mbar_wait(mbar, (s - 1) & 1);     // frees buffer (s+1)&1
        if (s + 1 < S) {
            stage_load(sbase + ((s + 1) & 1) * STAGE_B, Ah, Al, Bh, Bl,
                       bm, bn, N, K, (s + 1) * GKC, tid);
            asm volatile("cp.async.commit_group;");
            asm volatile("cp.async.wait_group 1;");
        } else {
            asm volatile("cp.async.wait_group 0;");
        }
        __syncthreads();

        if (warp == 0) {
            asm volatile("fence.proxy.async.shared::cta;" ::: "memory");
            if (elect_one()) {
                uint32_t st = sbase + (s & 1) * STAGE_B;
                uint64_t dah = mk_desc(st);
                uint64_t dal = mk_desc(st + PLANE_B);
                uint64_t dbh = mk_desc(st + 2 * PLANE_B);
                uint64_t dbl = mk_desc(st + 3 * PLANE_B);
                bool first = (s == 0);
                #pragma unroll
                for (int ks = 0; ks < 4; ks++)
                    tc05_mma_f16_ss(tmem, dah + ks * 2, dbh + ks * 2, IDESC_F16,
                                    (first && ks == 0) ? 0u : 1u);
                #pragma unroll
                for (int ks = 0; ks < 4; ks++)
                    tc05_mma_f16_ss(tmem, dah + ks * 2, dbl + ks * 2, IDESC_F16, 1u);
                #pragma unroll
                for (int ks = 0; ks < 4; ks++)
                    tc05_mma_f16_ss(tmem, dal + ks * 2, dbh + ks * 2, IDESC_F16, 1u);
                asm volatile(
                    "tcgen05.commit.cta_group::1.mbarrier::arrive::one.shared::cluster.b64 [%0];"
                    :: "r"(mbar) : "memory");
            }
        }
    }

    mbar_wait(mbar, (S - 1) & 1);
    asm volatile("tcgen05.fence::after_thread_sync;" ::: "memory");

    // epilogue: 8 warps, warp w -> subpartition w&3, column half w>>2
    {
        int sub = warp & 3, chf = warp >> 2;
        int row = bm + sub * 32 + lane;
        #pragma unroll
        for (int g = 0; g < 2; g++) {
            uint32_t dr[32];
            ldtm_x32(dr, tmem + chf * 64 + g * 32);
            asm volatile("tcgen05.wait::ld.sync.aligned;" ::: "memory");
            int col0 = bn + chf * 64 + g * 32;
            #pragma unroll
            for (int c = 0; c < 32; c++) {
                int col = col0 + c;
                if (col < N) {
                    float v = __uint_as_float(dr[c]);
                    if (bias) v += bias[col];
                    if (act) v = gelu_f(v);
                    if (Ch) {
                        __half h, lo;
                        split_h(v, h, lo);
                        Ch[(size_t)row * N + col] = h;
                        Cl[(size_t)row * N + col] = lo;
                    } else {
                        if (res) v += res[(size_t)row * N + col];
                        Cf[(size_t)row * N + col] = v;
                    }
                }
            }
        }
    }

    __syncthreads();
    if (tid == 0) {
        asm volatile("mbarrier.inval.shared.b64 [%0];" :: "r"(mbar) : "memory");
    }
    if (warp == 0) {
        asm volatile("tcgen05.dealloc.cta_group::1.sync.aligned.b32 %0, %1;"
                     :: "r"(tmem), "r"(128u));
    }

#else
    // ================= mma.sync fallback (sm_103 base target) =================
    int g = lane >> 2, t4 = lane & 3;
    int wm = (warp & 1) * 64;          // 2 m-warps x 4 n-warps
    int wn = (warp >> 1) * 32;

    float c[4][4][4] = {};

    stage_load(sbase, Ah, Al, Bh, Bl, bm, bn, N, K, 0, tid);
    asm volatile("cp.async.commit_group;");

    for (int s = 0; s < S; s++) {
        if (s + 1 < S) {
            stage_load(sbase + ((s + 1) & 1) * STAGE_B, Ah, Al, Bh, Bl,
                       bm, bn, N, K, (s + 1) * GKC, tid);
            asm volatile("cp.async.commit_group;");
            asm volatile("cp.async.wait_group 1;");
        } else {
            asm volatile("cp.async.wait_group 0;");
        }
        __syncthreads();

        const char* st = dsm + ((smem_u32(dsm) + 1023 & ~1023u) - smem_u32(dsm))
                         + (s & 1) * STAGE_B;
        #pragma unroll
        for (int kk = 0; kk < 4; kk++) {      // K16 steps within the K64 stage
            int kw = kk * 8;                  // word offset of this K16 step
            unsigned ah[4][4], al[4][4];
            #pragma unroll
            for (int im = 0; im < 4; im++) {
                int r0 = wm + im * 16 + g, r8 = r0 + 8;
                ah[im][0] = *(const unsigned*)(st + swz(r0 * 128 + (kw + t4) * 4));
                ah[im][1] = *(const unsigned*)(st + swz(r8 * 128 + (kw + t4) * 4));
                ah[im][2] = *(const unsigned*)(st + swz(r0 * 128 + (kw + 4 + t4) * 4));
                ah[im][3] = *(const unsigned*)(st + swz(r8 * 128 + (kw + 4 + t4) * 4));
                al[im][0] = *(const unsigned*)(st + PLANE_B + swz(r0 * 128 + (kw + t4) * 4));
                al[im][1] = *(const unsigned*)(st + PLANE_B + swz(r8 * 128 + (kw + t4) * 4));
                al[im][2] = *(const unsigned*)(st + PLANE_B + swz(r0 * 128 + (kw + 4 + t4) * 4));
                al[im][3] = *(const unsigned*)(st + PLANE_B + swz(r8 * 128 + (kw + 4 + t4) * 4));
            }
            #pragma unroll
            for (int jn = 0; jn < 4; jn++) {
                int n = wn + jn * 8 + g;
                unsigned bh0 = *(const unsigned*)(st + 2 * PLANE_B + swz(n * 128 + (kw + t4) * 4));
                unsigned bh1 = *(const unsigned*)(st + 2 * PLANE_B + swz(n * 128 + (kw + 4 + t4) * 4));
                unsigned bl0 = *(const unsigned*)(st + 3 * PLANE_B + swz(n * 128 + (kw + t4) * 4));
                unsigned bl1 = *(const unsigned*)(st + 3 * PLANE_B + swz(n * 128 + (kw + 4 + t4) * 4));
                #pragma unroll
                for (int im = 0; im < 4; im++) {
                    mma_f16(c[im][jn], ah[im], bh0, bh1);
                    mma_f16(c[im][jn], ah[im], bl0, bl1);
                    mma_f16(c[im][jn], al[im], bh0, bh1);
                }
            }
        }
        __syncthreads();
    }

    #pragma unroll
    for (int im = 0; im < 4; im++) {
        #pragma unroll
        for (int jn = 0; jn < 4; jn++) {
            int row0 = bm + wm + im * 16 + g;
            int col0 = bn + wn + jn * 8 + t4 * 2;
            #pragma unroll
            for (int p = 0; p < 4; p++) {
                int row = row0 + (p >> 1) * 8;
                int col = col0 + (p & 1);
                if (col < N) {
                    float v = c[im][jn][p];
                    if (bias) v += bias[col];
                    if (act) v = gelu_f(v);
                    if (Ch) {
                        __half h, lo;
                        split_h(v, h, lo);
                        Ch[(size_t)row * N + col] = h;
                        Cl[(size_t)row * N + col] = lo;
                    } else {
                        if (res) v += res[(size_t)row * N + col];
                        Cf[(size_t)row * N + col] = v;
                    }
                }
            }
        }
    }
#endif
}

// =====================================================================
// Causal attention -> fp16 hi/lo planes
// =====================================================================
__global__ void attn_kernel(const float* __restrict__ qkv,
                            __half* __restrict__ yh, __half* __restrict__ yl) {
    int q = blockIdx.x;
    int h = blockIdx.y;
    int b = blockIdx.z;
    int tid = threadIdx.x;

    __shared__ float qs[ND];
    __shared__ float sc[NT];
    __shared__ float red[32];
    __shared__ float yp[2][ND];

    const size_t rs = 3 * NC;
    const float* qptr = qkv + ((size_t)(b * NT + q)) * rs + h * ND;
    if (tid < ND) qs[tid] = qptr[tid];
    __syncthreads();

    const float scale = 0.125f;
    int nk = q + 1;
    const float* kbase = qkv + ((size_t)b * NT) * rs + NC + h * ND;
    for (int k = tid; k < nk; k += blockDim.x) {
        const float* kp = kbase + (size_t)k * rs;
        float d = 0.f;
        #pragma unroll
        for (int i = 0; i < ND; i++) d = fmaf(qs[i], kp[i], d);
        sc[k] = d * scale;
    }
    __syncthreads();

    float m = -1e30f;
    for (int k = tid; k < nk; k += blockDim.x) m = fmaxf(m, sc[k]);
    #pragma unroll
    for (int o = 16; o; o >>= 1) m = fmaxf(m, __shfl_xor_sync(0xffffffffu, m, o));
    if ((tid & 31) == 0) red[tid >> 5] = m;
    __syncthreads();
    if (tid < 32) {
        float v = (tid < (int)(blockDim.x >> 5)) ? red[tid] : -1e30f;
        #pragma unroll
        for (int o = 16; o; o >>= 1) v = fmaxf(v, __shfl_xor_sync(0xffffffffu, v, o));
        if (tid == 0) red[0] = v;
    }
    __syncthreads();
    m = red[0];
    __syncthreads();

    float s = 0.f;
    for (int k = tid; k < nk; k += blockDim.x) {
        float e = __expf(sc[k] - m);
        sc[k] = e;
        s += e;
    }
    #pragma unroll
    for (int o = 16; o; o >>= 1) s += __shfl_xor_sync(0xffffffffu, s, o);
    if ((tid & 31) == 0) red[tid >> 5] = s;
    __syncthreads();
    if (tid < 32) {
        float v = (tid < (int)(blockDim.x >> 5)) ? red[tid] : 0.f;
        #pragma unroll
        for (int o = 16; o; o >>= 1) v += __shfl_xor_sync(0xffffffffu, v, o);
        if (tid == 0) red[0] = v;
    }
    __syncthreads();
    float inv = 1.0f / red[0];

    int part = tid >> 6, d = tid & 63;
    const float* vbase = qkv + ((size_t)b * NT) * rs + 2 * NC + h * ND;
    float acc = 0.f;
    for (int k = part; k < nk; k += 2)
        acc = fmaf(sc[k], vbase[(size_t)k * rs + d], acc);
    yp[part][d] = acc;
    __syncthreads();
    if (tid < ND) {
        float v = (yp[0][tid] + yp[1][tid]) * inv;
        __half hh, lo;
        split_h(v, hh, lo);
        size_t o = ((size_t)(b * NT + q)) * NC + h * ND + tid;
        yh[o] = hh;
        yl[o] = lo;
    }
}

// =====================================================================
// launch
// =====================================================================
extern "C" void kernel_launch(void* const* d_in, const int* in_sizes, int n_in,
                              void* d_out, int out_size) {
    const int*   idx    = (const int*)d_in[0];
    const float* wte    = (const float*)d_in[1];
    const float* wpe    = (const float*)d_in[2];
    const float* ln1_w  = (const float*)d_in[3];
    const float* ln1_b  = (const float*)d_in[4];
    const float* ln2_w  = (const float*)d_in[5];
    const float* ln2_b  = (const float*)d_in[6];
    const float* attn_w = (const float*)d_in[7];
    const float* attn_b = (const float*)d_in[8];
    const float* proj_w = (const float*)d_in[9];
    const float* proj_b = (const float*)d_in[10];
    const float* fc_w   = (const float*)d_in[11];
    const float* fc_b   = (const float*)d_in[12];
    const float* fcp_w  = (const float*)d_in[13];
    const float* fcp_b  = (const float*)d_in[14];
    const float* lnf_w  = (const float*)d_in[15];
    const float* lnf_b  = (const float*)d_in[16];
    const float* lmh    = (const float*)d_in[17];
    float* out = (float*)d_out;

    float *x, *qkv;
    __half *xh, *xl, *yh, *yl;
    cudaGetSymbolAddress((void**)&x, g_x);
    cudaGetSymbolAddress((void**)&qkv, g_qkv);
    cudaGetSymbolAddress((void**)&xh, g_xh);
    cudaGetSymbolAddress((void**)&xl, g_xl);
    cudaGetSymbolAddress((void**)&yh, g_yh);
    cudaGetSymbolAddress((void**)&yl, g_yl);

    __half *wa_h, *wa_l, *wp_h, *wp_l, *wf_h, *wf_l, *wq_h, *wq_l, *lm_h, *lm_l;
    cudaGetSymbolAddress((void**)&wa_h, g_wa_h);
    cudaGetSymbolAddress((void**)&wa_l, g_wa_l);
    cudaGetSymbolAddress((void**)&wp_h, g_wp_h);
    cudaGetSymbolAddress((void**)&wp_l, g_wp_l);
    cudaGetSymbolAddress((void**)&wf_h, g_wf_h);
    cudaGetSymbolAddress((void**)&wf_l, g_wf_l);
    cudaGetSymbolAddress((void**)&wq_h, g_wq_h);
    cudaGetSymbolAddress((void**)&wq_l, g_wq_l);
    cudaGetSymbolAddress((void**)&lm_h, g_lm_h);
    cudaGetSymbolAddress((void**)&lm_l, g_lm_l);

    cudaFuncSetAttribute(tc05_gemm, cudaFuncAttributeMaxDynamicSharedMemorySize,
                         GSMEM_BYTES);

    // ---- weight conversion ----
    dim3 tb(32, 8);
    transpose_split<<<dim3(2304 / 32, 768 / 32, 12), tb>>>(attn_w, wa_h, wa_l, NC, 3 * NC);
    transpose_split<<<dim3(768 / 32, 768 / 32, 12), tb>>>(proj_w, wp_h, wp_l, NC, NC);
    transpose_split<<<dim3(3072 / 32, 768 / 32, 12), tb>>>(fc_w, wf_h, wf_l, NC, 4 * NC);
    transpose_split<<<dim3(768 / 32, 3072 / 32, 12), tb>>>(fcp_w, wq_h, wq_l, 4 * NC, NC);
    split_kernel<<<(NV * NC + 255) / 256, 256>>>(lmh, lm_h, lm_l, NV * NC);

    embed_kernel<<<NTOK, 256>>>(idx, wte, wpe, x);

    for (int l = 0; l < NL; l++) {
        ln_kernel<<<NTOK, 256>>>(x, ln1_w + l * NC, ln1_b + l * NC, xh, xl);
        // qkv = act @ attn_w^T + attn_b  (fp32 out)
        tc05_gemm<<<dim3(NTOK / GBM, (3 * NC) / GBN), 256, GSMEM_BYTES>>>(
            xh, xl, wa_h + (size_t)l * 3 * NC * NC, wa_l + (size_t)l * 3 * NC * NC,
            attn_b + (size_t)l * 3 * NC, nullptr, qkv, nullptr, nullptr,
            NTOK, 3 * NC, NC, 0);
        {
            dim3 grid(NT, NH, NB);
            attn_kernel<<<grid, 128>>>(qkv, xh, xl);
        }
        // x = x + y @ proj_w^T + proj_b
        tc05_gemm<<<dim3(NTOK / GBM, NC / GBN), 256, GSMEM_BYTES>>>(
            xh, xl, wp_h + (size_t)l * NC * NC, wp_l + (size_t)l * NC * NC,
            proj_b + (size_t)l * NC, x, x, nullptr, nullptr,
            NTOK, NC, NC, 0);
        ln_kernel<<<NTOK, 256>>>(x, ln2_w + l * NC, ln2_b + l * NC, xh, xl);
        // fc = gelu(act @ fc_w^T + fc_b) -> fp16 planes
        tc05_gemm<<<dim3(NTOK / GBM, (4 * NC) / GBN), 256, GSMEM_BYTES>>>(
            xh, xl, wf_h + (size_t)l * 4 * NC * NC, wf_l + (size_t)l * 4 * NC * NC,
            fc_b + (size_t)l * 4 * NC, nullptr, nullptr, yh, yl,
            NTOK, 4 * NC, NC, 1);
        // x = x + fc @ fcp_w^T + fcp_b
        tc05_gemm<<<dim3(NTOK / GBM, NC / GBN), 256, GSMEM_BYTES>>>(
            yh, yl, wq_h + (size_t)l * NC * 4 * NC, wq_l + (size_t)l * NC * 4 * NC,
            fcp_b + (size_t)l * NC, x, x, nullptr, nullptr,
            NTOK, NC, 4 * NC, 0);
    }

    ln_kernel<<<NTOK, 256>>>(x, lnf_w, lnf_b, xh, xl);

    // logits = act @ lm_head^T  (m-fastest grid for B-tile L2 reuse)
    tc05_gemm<<<dim3(NTOK / GBM, (NV + GBN - 1) / GBN), 256, GSMEM_BYTES>>>(
        xh, xl, lm_h, lm_l, nullptr, nullptr, out, nullptr, nullptr,
        NTOK, NV, NC, 0);
}